// round 2
// baseline (speedup 1.0000x reference)
#include <cuda_runtime.h>
#include <stdint.h>

// EmbeddingDropout: out[r, :] = weight[x[r], :] * mask[x[r]]
// x: [16384] indices (harness materializes int64 as int32),
// weight: [50257, 512] f32, mask: [50257] f32. Output: [16384, 512] f32.
//
// Pure HBM-bound gather. 1 block = 2 rows, 128 threads/row,
// each thread moves one float4 (16 B). Fully coalesced read & write.

#define D 512
#define D4 (D / 4)                       // 128 float4 per row
#define ROWS_PER_BLOCK 2
#define THREADS (D4 * ROWS_PER_BLOCK)    // 256

__global__ __launch_bounds__(THREADS) void embedding_dropout_kernel(
    const int* __restrict__ x,           // [N] int32 token ids
    const float4* __restrict__ weight,   // [V, D4]
    const float* __restrict__ mask,      // [V]
    float4* __restrict__ out,            // [N, D4]
    int n_rows)
{
    int local_row = threadIdx.x >> 7;          // /128 -> 0..1
    int lane      = threadIdx.x & (D4 - 1);    // 0..127
    int row = blockIdx.x * ROWS_PER_BLOCK + local_row;
    if (row >= n_rows) return;

    int idx = x[row];                          // broadcast within half-block
    float scale = mask[idx];

    float4 v = weight[(size_t)idx * D4 + lane];
    v.x *= scale; v.y *= scale; v.z *= scale; v.w *= scale;
    out[(size_t)row * D4 + lane] = v;
}

extern "C" void kernel_launch(void* const* d_in, const int* in_sizes, int n_in,
                              void* d_out, int out_size)
{
    // Identify inputs by element count (robust to ordering surprises):
    //   x: B*S = 16384, weight: V*D = 25731584, mask: V = 50257.
    const int*    x    = nullptr;
    const float4* w    = nullptr;
    const float*  mask = nullptr;
    int n_rows = 0;

    long long max_sz = -1, mid_sz = -1;
    int wi = -1, mi = -1, xi = -1;
    for (int i = 0; i < n_in; i++) {
        if (in_sizes[i] > max_sz) { max_sz = in_sizes[i]; wi = i; }
    }
    for (int i = 0; i < n_in; i++) {
        if (i != wi && in_sizes[i] > mid_sz) { mid_sz = in_sizes[i]; mi = i; }
    }
    for (int i = 0; i < n_in; i++) {
        if (i != wi && i != mi) { xi = i; break; }
    }

    x    = (const int*)d_in[xi];
    w    = (const float4*)d_in[wi];
    mask = (const float*)d_in[mi];
    n_rows = in_sizes[xi];

    float4* out = (float4*)d_out;
    int blocks = (n_rows + ROWS_PER_BLOCK - 1) / ROWS_PER_BLOCK;

    embedding_dropout_kernel<<<blocks, THREADS>>>(x, w, mask, out, n_rows);
}

// round 3
// speedup vs baseline: 1.0060x; 1.0060x over previous
#include <cuda_runtime.h>
#include <stdint.h>

// EmbeddingDropout: out[r, :] = weight[x[r], :] * mask[x[r]]
// x: [16384] int32 token ids, weight: [50257, 512] f32, mask: [50257] f32.
// Output: [16384, 512] f32.
//
// R3: latency-limited before (MLP=1/warp on weight load). Now one WARP per
// row: each thread moves 4 float4 (lane + 32*i) -> 4 independent LDG.128 in
// flight per thread. Streaming stores (__stcs) keep the write-once output
// from evicting weight rows in L2.

#define D 512
#define D4 (D / 4)            // 128 float4 per row
#define THREADS 256           // 8 warps -> 8 rows per block
#define ROWS_PER_BLOCK (THREADS / 32)

__global__ __launch_bounds__(THREADS) void embedding_dropout_kernel(
    const int* __restrict__ x,           // [N]
    const float4* __restrict__ weight,   // [V, D4]
    const float* __restrict__ mask,      // [V]
    float4* __restrict__ out,            // [N, D4]
    int n_rows)
{
    int row  = (blockIdx.x * THREADS + threadIdx.x) >> 5;  // one warp per row
    int lane = threadIdx.x & 31;
    if (row >= n_rows) return;

    int idx = __ldg(&x[row]);            // L1 broadcast across the warp
    float s = __ldg(&mask[idx]);

    const float4* wrow = weight + (size_t)idx * D4;
    float4*       orow = out    + (size_t)row * D4;

    float4 v[4];
    #pragma unroll
    for (int i = 0; i < 4; i++)          // 4 independent 512B-coalesced loads
        v[i] = __ldg(&wrow[lane + 32 * i]);

    #pragma unroll
    for (int i = 0; i < 4; i++) {
        v[i].x *= s; v[i].y *= s; v[i].z *= s; v[i].w *= s;
        __stcs(&orow[lane + 32 * i], v[i]);   // streaming: evict-first in L2
    }
}

extern "C" void kernel_launch(void* const* d_in, const int* in_sizes, int n_in,
                              void* d_out, int out_size)
{
    // Identify inputs by element count: x=16384, weight=25731584, mask=50257.
    long long max_sz = -1, mid_sz = -1;
    int wi = -1, mi = -1, xi = -1;
    for (int i = 0; i < n_in; i++)
        if (in_sizes[i] > max_sz) { max_sz = in_sizes[i]; wi = i; }
    for (int i = 0; i < n_in; i++)
        if (i != wi && in_sizes[i] > mid_sz) { mid_sz = in_sizes[i]; mi = i; }
    for (int i = 0; i < n_in; i++)
        if (i != wi && i != mi) { xi = i; break; }

    const int*    x    = (const int*)d_in[xi];
    const float4* w    = (const float4*)d_in[wi];
    const float*  mask = (const float*)d_in[mi];
    float4*       out  = (float4*)d_out;
    int n_rows = in_sizes[xi];

    int blocks = (n_rows + ROWS_PER_BLOCK - 1) / ROWS_PER_BLOCK;
    embedding_dropout_kernel<<<blocks, THREADS>>>(x, w, mask, out, n_rows);
}